// round 1
// baseline (speedup 1.0000x reference)
#include <cuda_runtime.h>
#include <cstdint>

#define D   256
#define BM  64
#define BK  32
#define NT  256

// ---- packed f32x2 helpers (Blackwell FFMA2 path, PTX-only) ----
__device__ __forceinline__ unsigned long long pack2(float x) {
    unsigned long long r;
    unsigned u = __float_as_uint(x);
    asm("mov.b64 %0, {%1, %1};" : "=l"(r) : "r"(u));
    return r;
}
__device__ __forceinline__ void ffma2(unsigned long long& d,
                                      unsigned long long a,
                                      unsigned long long b) {
    asm("fma.rn.f32x2 %0, %1, %2, %0;" : "+l"(d) : "l"(a), "l"(b));
}
__device__ __forceinline__ float2 unpack2(unsigned long long v) {
    float2 f;
    asm("mov.b64 {%0, %1}, %2;" : "=f"(f.x), "=f"(f.y) : "l"(v));
    return f;
}

// Fused: gather -> hadamard -> GEMM1(+b1,relu) -> dot(W2)+b2 -> scores
__global__ __launch_bounds__(NT, 1)
void mlpdec_kernel(const float* __restrict__ h,
                   const void* __restrict__ edges_raw,
                   const float* __restrict__ W1,
                   const float* __restrict__ b1,
                   const float* __restrict__ W2,
                   const float* __restrict__ b2,
                   float* __restrict__ out,
                   int E)
{
    extern __shared__ float smem[];
    float* hadT = smem;                 // [256][64]  (k-major, transposed) 64KB
    float* w1s  = smem + D * BM;        // [2][32][256] double buffer      64KB

    const int tid = threadIdx.x;
    const int e0  = blockIdx.x * BM;
    const int eg  = tid & 15;           // edge group (4 rows each)
    const int cg  = tid >> 4;           // column group (16 cols each)

    // ---- edge dtype probe: int64 little-endian of values <100000 has all-zero
    //      odd dwords; int32 layout puts random indices there. Deterministic. ----
    const int* w32 = (const int*)edges_raw;
    bool is64 = true;
    #pragma unroll
    for (int i = 0; i < 8; i++) {
        if (w32[2 * i + 1] != 0) { is64 = false; break; }
    }

    // ---- gather endpoints + hadamard, store transposed into smem ----
    {
        int row  = tid & 63;
        int quad = tid >> 6;            // 0..3
        long long e = (long long)e0 + row;
        long long s = 0, d = 0;
        if (e < E) {
            if (is64) {
                const long long* e64 = (const long long*)edges_raw;
                s = e64[2 * e];
                d = e64[2 * e + 1];
            } else {
                s = w32[2 * e];
                d = w32[2 * e + 1];
            }
        }
        const float4* hs = (const float4*)(h + s * D);
        const float4* hd = (const float4*)(h + d * D);
        #pragma unroll
        for (int i = 0; i < 16; i++) {
            int c4 = quad * 16 + i;
            float4 a = hs[c4];
            float4 b = hd[c4];
            int kb = c4 * 4;
            // STS: warp = 32 consecutive rows at fixed k -> conflict free
            hadT[(kb + 0) * BM + row] = a.x * b.x;
            hadT[(kb + 1) * BM + row] = a.y * b.y;
            hadT[(kb + 2) * BM + row] = a.z * b.z;
            hadT[(kb + 3) * BM + row] = a.w * b.w;
        }
    }

    // ---- preload W1 tile 0 ----
    {
        const float4* src = (const float4*)W1;
        float4* dst = (float4*)w1s;
        #pragma unroll
        for (int t = 0; t < 8; t++) dst[tid + t * NT] = src[tid + t * NT];
    }
    __syncthreads();

    // ---- main GEMM: acc[4 rows][8 col-pairs] in packed f32x2 ----
    unsigned long long acc[4][8];
    #pragma unroll
    for (int i = 0; i < 4; i++)
        #pragma unroll
        for (int j = 0; j < 8; j++) acc[i][j] = 0ull;

    float4 stage[8];
    #pragma unroll 1
    for (int kt = 0; kt < 8; kt++) {
        // issue loads for next tile before computing this one
        if (kt < 7) {
            const float4* src = (const float4*)(W1 + (kt + 1) * BK * D);
            #pragma unroll
            for (int t = 0; t < 8; t++) stage[t] = src[tid + t * NT];
        }
        const float* wbuf = w1s + (kt & 1) * (BK * D);
        #pragma unroll 8
        for (int k = 0; k < BK; k++) {
            const float4 a4 = *(const float4*)(hadT + (kt * BK + k) * BM + eg * 4);
            unsigned long long pa0 = pack2(a4.x);
            unsigned long long pa1 = pack2(a4.y);
            unsigned long long pa2 = pack2(a4.z);
            unsigned long long pa3 = pack2(a4.w);
            const float* brow = wbuf + k * D + cg * 16;
            ulonglong2 q0 = *(const ulonglong2*)(brow);
            ulonglong2 q1 = *(const ulonglong2*)(brow + 4);
            ulonglong2 q2 = *(const ulonglong2*)(brow + 8);
            ulonglong2 q3 = *(const ulonglong2*)(brow + 12);
            unsigned long long bb[8] = {q0.x, q0.y, q1.x, q1.y,
                                        q2.x, q2.y, q3.x, q3.y};
            #pragma unroll
            for (int j = 0; j < 8; j++) {
                ffma2(acc[0][j], pa0, bb[j]);
                ffma2(acc[1][j], pa1, bb[j]);
                ffma2(acc[2][j], pa2, bb[j]);
                ffma2(acc[3][j], pa3, bb[j]);
            }
        }
        if (kt < 7) {
            float4* dst = (float4*)(w1s + ((kt + 1) & 1) * (BK * D));
            #pragma unroll
            for (int t = 0; t < 8; t++) dst[tid + t * NT] = stage[t];
            __syncthreads();
        }
    }

    // ---- epilogue: +b1, relu, dot with W2 -> per-thread partials ----
    float b1r[16], w2r[16];
    #pragma unroll
    for (int j = 0; j < 16; j++) {
        b1r[j] = b1[cg * 16 + j];
        w2r[j] = W2[cg * 16 + j];
    }
    float p[4] = {0.f, 0.f, 0.f, 0.f};
    #pragma unroll
    for (int i = 0; i < 4; i++) {
        #pragma unroll
        for (int j = 0; j < 8; j++) {
            float2 v = unpack2(acc[i][j]);
            float h0 = v.x + b1r[2 * j];
            float h1 = v.y + b1r[2 * j + 1];
            h0 = h0 > 0.f ? h0 : 0.f;
            h1 = h1 > 0.f ? h1 : 0.f;
            p[i] += h0 * w2r[2 * j] + h1 * w2r[2 * j + 1];
        }
    }

    // ---- cross-column-group reduction through smem (reuse w1s) ----
    __syncthreads();
    float* red = w1s;                   // [16][64]
    #pragma unroll
    for (int i = 0; i < 4; i++) red[cg * BM + eg * 4 + i] = p[i];
    __syncthreads();

    if (tid < BM) {
        float s = b2[0];
        #pragma unroll
        for (int c = 0; c < 16; c++) s += red[c * BM + tid];
        int e = e0 + tid;
        if (e < E) out[e] = s;
    }
}

extern "C" void kernel_launch(void* const* d_in, const int* in_sizes, int n_in,
                              void* d_out, int out_size)
{
    const float* h     = (const float*)d_in[0];
    const void*  edges = (const void*)d_in[1];
    const float* W1    = (const float*)d_in[2];
    const float* b1    = (const float*)d_in[3];
    const float* W2    = (const float*)d_in[4];
    const float* b2    = (const float*)d_in[5];
    float* out = (float*)d_out;

    int E = in_sizes[1] / 2;            // edges is [E,2]
    int grid = (E + BM - 1) / BM;
    size_t smem = (size_t)(D * BM + 2 * BK * D) * sizeof(float);  // 128 KB

    cudaFuncSetAttribute(mlpdec_kernel,
                         cudaFuncAttributeMaxDynamicSharedMemorySize,
                         (int)smem);
    mlpdec_kernel<<<grid, NT, smem>>>(h, edges, W1, b1, W2, b2, out, E);
}

// round 2
// speedup vs baseline: 1.0000x; 1.0000x over previous
#include <cuda_runtime.h>
#include <cstdint>

#define D   256
#define BM  64
#define BK  32
#define NT  256

// ---- packed f32x2 helpers (Blackwell FFMA2 path, PTX-only) ----
__device__ __forceinline__ unsigned long long pack2(float x) {
    unsigned long long r;
    unsigned u = __float_as_uint(x);
    asm("mov.b64 %0, {%1, %1};" : "=l"(r) : "r"(u));
    return r;
}
__device__ __forceinline__ void ffma2(unsigned long long& d,
                                      unsigned long long a,
                                      unsigned long long b) {
    asm("fma.rn.f32x2 %0, %1, %2, %0;" : "+l"(d) : "l"(a), "l"(b));
}
__device__ __forceinline__ float2 unpack2(unsigned long long v) {
    float2 f;
    asm("mov.b64 {%0, %1}, %2;" : "=f"(f.x), "=f"(f.y) : "l"(v));
    return f;
}

// Fused: gather -> hadamard -> GEMM1(+b1,relu) -> dot(W2)+b2 -> scores
__global__ __launch_bounds__(NT, 1)
void mlpdec_kernel(const float* __restrict__ h,
                   const void* __restrict__ edges_raw,
                   const float* __restrict__ W1,
                   const float* __restrict__ b1,
                   const float* __restrict__ W2,
                   const float* __restrict__ b2,
                   float* __restrict__ out,
                   int E)
{
    extern __shared__ float smem[];
    float* hadT = smem;                 // [256][64]  (k-major, transposed) 64KB
    float* w1s  = smem + D * BM;        // [2][32][256] double buffer      64KB

    const int tid = threadIdx.x;
    const int e0  = blockIdx.x * BM;
    const int eg  = tid & 15;           // edge group (4 rows each)
    const int cg  = tid >> 4;           // column group (16 cols each)

    // ---- edge dtype probe: int64 little-endian of values <100000 has all-zero
    //      odd dwords; int32 layout puts random indices there. Deterministic. ----
    const int* w32 = (const int*)edges_raw;
    bool is64 = true;
    #pragma unroll
    for (int i = 0; i < 8; i++) {
        if (w32[2 * i + 1] != 0) { is64 = false; break; }
    }

    // ---- gather endpoints + hadamard, store transposed into smem ----
    {
        int row  = tid & 63;
        int quad = tid >> 6;            // 0..3
        long long e = (long long)e0 + row;
        long long s = 0, d = 0;
        if (e < E) {
            if (is64) {
                const long long* e64 = (const long long*)edges_raw;
                s = e64[2 * e];
                d = e64[2 * e + 1];
            } else {
                s = w32[2 * e];
                d = w32[2 * e + 1];
            }
        }
        const float4* hs = (const float4*)(h + s * D);
        const float4* hd = (const float4*)(h + d * D);
        #pragma unroll
        for (int i = 0; i < 16; i++) {
            int c4 = quad * 16 + i;
            float4 a = hs[c4];
            float4 b = hd[c4];
            int kb = c4 * 4;
            // STS: warp = 32 consecutive rows at fixed k -> conflict free
            hadT[(kb + 0) * BM + row] = a.x * b.x;
            hadT[(kb + 1) * BM + row] = a.y * b.y;
            hadT[(kb + 2) * BM + row] = a.z * b.z;
            hadT[(kb + 3) * BM + row] = a.w * b.w;
        }
    }

    // ---- preload W1 tile 0 ----
    {
        const float4* src = (const float4*)W1;
        float4* dst = (float4*)w1s;
        #pragma unroll
        for (int t = 0; t < 8; t++) dst[tid + t * NT] = src[tid + t * NT];
    }
    __syncthreads();

    // ---- main GEMM: acc[4 rows][8 col-pairs] in packed f32x2 ----
    unsigned long long acc[4][8];
    #pragma unroll
    for (int i = 0; i < 4; i++)
        #pragma unroll
        for (int j = 0; j < 8; j++) acc[i][j] = 0ull;

    float4 stage[8];
    #pragma unroll 1
    for (int kt = 0; kt < 8; kt++) {
        // issue loads for next tile before computing this one
        if (kt < 7) {
            const float4* src = (const float4*)(W1 + (kt + 1) * BK * D);
            #pragma unroll
            for (int t = 0; t < 8; t++) stage[t] = src[tid + t * NT];
        }
        const float* wbuf = w1s + (kt & 1) * (BK * D);
        #pragma unroll 8
        for (int k = 0; k < BK; k++) {
            const float4 a4 = *(const float4*)(hadT + (kt * BK + k) * BM + eg * 4);
            unsigned long long pa0 = pack2(a4.x);
            unsigned long long pa1 = pack2(a4.y);
            unsigned long long pa2 = pack2(a4.z);
            unsigned long long pa3 = pack2(a4.w);
            const float* brow = wbuf + k * D + cg * 16;
            ulonglong2 q0 = *(const ulonglong2*)(brow);
            ulonglong2 q1 = *(const ulonglong2*)(brow + 4);
            ulonglong2 q2 = *(const ulonglong2*)(brow + 8);
            ulonglong2 q3 = *(const ulonglong2*)(brow + 12);
            unsigned long long bb[8] = {q0.x, q0.y, q1.x, q1.y,
                                        q2.x, q2.y, q3.x, q3.y};
            #pragma unroll
            for (int j = 0; j < 8; j++) {
                ffma2(acc[0][j], pa0, bb[j]);
                ffma2(acc[1][j], pa1, bb[j]);
                ffma2(acc[2][j], pa2, bb[j]);
                ffma2(acc[3][j], pa3, bb[j]);
            }
        }
        if (kt < 7) {
            float4* dst = (float4*)(w1s + ((kt + 1) & 1) * (BK * D));
            #pragma unroll
            for (int t = 0; t < 8; t++) dst[tid + t * NT] = stage[t];
            __syncthreads();
        }
    }

    // ---- epilogue: +b1, relu, dot with W2 -> per-thread partials ----
    float b1r[16], w2r[16];
    #pragma unroll
    for (int j = 0; j < 16; j++) {
        b1r[j] = b1[cg * 16 + j];
        w2r[j] = W2[cg * 16 + j];
    }
    float p[4] = {0.f, 0.f, 0.f, 0.f};
    #pragma unroll
    for (int i = 0; i < 4; i++) {
        #pragma unroll
        for (int j = 0; j < 8; j++) {
            float2 v = unpack2(acc[i][j]);
            float h0 = v.x + b1r[2 * j];
            float h1 = v.y + b1r[2 * j + 1];
            h0 = h0 > 0.f ? h0 : 0.f;
            h1 = h1 > 0.f ? h1 : 0.f;
            p[i] += h0 * w2r[2 * j] + h1 * w2r[2 * j + 1];
        }
    }

    // ---- cross-column-group reduction through smem (reuse w1s) ----
    __syncthreads();
    float* red = w1s;                   // [16][64]
    #pragma unroll
    for (int i = 0; i < 4; i++) red[cg * BM + eg * 4 + i] = p[i];
    __syncthreads();

    if (tid < BM) {
        float s = b2[0];
        #pragma unroll
        for (int c = 0; c < 16; c++) s += red[c * BM + tid];
        int e = e0 + tid;
        if (e < E) out[e] = s;
    }
}

extern "C" void kernel_launch(void* const* d_in, const int* in_sizes, int n_in,
                              void* d_out, int out_size)
{
    const float* h     = (const float*)d_in[0];
    const void*  edges = (const void*)d_in[1];
    const float* W1    = (const float*)d_in[2];
    const float* b1    = (const float*)d_in[3];
    const float* W2    = (const float*)d_in[4];
    const float* b2    = (const float*)d_in[5];
    float* out = (float*)d_out;

    int E = in_sizes[1] / 2;            // edges is [E,2]
    int grid = (E + BM - 1) / BM;
    size_t smem = (size_t)(D * BM + 2 * BK * D) * sizeof(float);  // 128 KB

    cudaFuncSetAttribute(mlpdec_kernel,
                         cudaFuncAttributeMaxDynamicSharedMemorySize,
                         (int)smem);
    mlpdec_kernel<<<grid, NT, smem>>>(h, edges, W1, b1, W2, b2, out, E);
}

// round 3
// speedup vs baseline: 1.0019x; 1.0019x over previous
#include <cuda_runtime.h>
#include <cstdint>

#define D   256
#define BM  64
#define BK  32
#define NT  256

// ---- packed f32x2 helpers (Blackwell FFMA2 path, PTX-only) ----
__device__ __forceinline__ unsigned long long pack2(float x) {
    unsigned long long r;
    unsigned u = __float_as_uint(x);
    asm("mov.b64 %0, {%1, %1};" : "=l"(r) : "r"(u));
    return r;
}
__device__ __forceinline__ void ffma2(unsigned long long& d,
                                      unsigned long long a,
                                      unsigned long long b) {
    asm("fma.rn.f32x2 %0, %1, %2, %0;" : "+l"(d) : "l"(a), "l"(b));
}
__device__ __forceinline__ float2 unpack2(unsigned long long v) {
    float2 f;
    asm("mov.b64 {%0, %1}, %2;" : "=f"(f.x), "=f"(f.y) : "l"(v));
    return f;
}

// Fused: gather -> hadamard -> GEMM1(+b1,relu) -> dot(W2)+b2 -> scores
__global__ __launch_bounds__(NT, 1)
void mlpdec_kernel(const float* __restrict__ h,
                   const void* __restrict__ edges_raw,
                   const float* __restrict__ W1,
                   const float* __restrict__ b1,
                   const float* __restrict__ W2,
                   const float* __restrict__ b2,
                   float* __restrict__ out,
                   int E)
{
    extern __shared__ float smem[];
    float* hadT = smem;                 // [256][64]  (k-major, transposed) 64KB
    float* w1s  = smem + D * BM;        // [2][32][256] double buffer      64KB

    const int tid = threadIdx.x;
    const int e0  = blockIdx.x * BM;
    const int eg  = tid & 15;           // edge group (4 rows each)
    const int cg  = tid >> 4;           // column group (16 cols each)

    // ---- edge dtype probe: int64 little-endian of values <100000 has all-zero
    //      odd dwords; int32 layout puts random indices there. Deterministic. ----
    const int* w32 = (const int*)edges_raw;
    bool is64 = true;
    #pragma unroll
    for (int i = 0; i < 8; i++) {
        if (w32[2 * i + 1] != 0) { is64 = false; break; }
    }

    // ---- gather endpoints + hadamard, store transposed into smem ----
    {
        int row  = tid & 63;
        int quad = tid >> 6;            // 0..3
        long long e = (long long)e0 + row;
        long long s = 0, d = 0;
        if (e < E) {
            if (is64) {
                const long long* e64 = (const long long*)edges_raw;
                s = e64[2 * e];
                d = e64[2 * e + 1];
            } else {
                s = w32[2 * e];
                d = w32[2 * e + 1];
            }
        }
        const float4* hs = (const float4*)(h + s * D);
        const float4* hd = (const float4*)(h + d * D);
        #pragma unroll
        for (int i = 0; i < 16; i++) {
            int c4 = quad * 16 + i;
            float4 a = hs[c4];
            float4 b = hd[c4];
            int kb = c4 * 4;
            // STS: warp = 32 consecutive rows at fixed k -> conflict free
            hadT[(kb + 0) * BM + row] = a.x * b.x;
            hadT[(kb + 1) * BM + row] = a.y * b.y;
            hadT[(kb + 2) * BM + row] = a.z * b.z;
            hadT[(kb + 3) * BM + row] = a.w * b.w;
        }
    }

    // ---- preload W1 tile 0 ----
    {
        const float4* src = (const float4*)W1;
        float4* dst = (float4*)w1s;
        #pragma unroll
        for (int t = 0; t < 8; t++) dst[tid + t * NT] = src[tid + t * NT];
    }
    __syncthreads();

    // ---- main GEMM: acc[4 rows][8 col-pairs] in packed f32x2 ----
    unsigned long long acc[4][8];
    #pragma unroll
    for (int i = 0; i < 4; i++)
        #pragma unroll
        for (int j = 0; j < 8; j++) acc[i][j] = 0ull;

    float4 stage[8];
    #pragma unroll 1
    for (int kt = 0; kt < 8; kt++) {
        // issue loads for next tile before computing this one
        if (kt < 7) {
            const float4* src = (const float4*)(W1 + (kt + 1) * BK * D);
            #pragma unroll
            for (int t = 0; t < 8; t++) stage[t] = src[tid + t * NT];
        }
        const float* wbuf = w1s + (kt & 1) * (BK * D);
        #pragma unroll 8
        for (int k = 0; k < BK; k++) {
            const float4 a4 = *(const float4*)(hadT + (kt * BK + k) * BM + eg * 4);
            unsigned long long pa0 = pack2(a4.x);
            unsigned long long pa1 = pack2(a4.y);
            unsigned long long pa2 = pack2(a4.z);
            unsigned long long pa3 = pack2(a4.w);
            const float* brow = wbuf + k * D + cg * 16;
            ulonglong2 q0 = *(const ulonglong2*)(brow);
            ulonglong2 q1 = *(const ulonglong2*)(brow + 4);
            ulonglong2 q2 = *(const ulonglong2*)(brow + 8);
            ulonglong2 q3 = *(const ulonglong2*)(brow + 12);
            unsigned long long bb[8] = {q0.x, q0.y, q1.x, q1.y,
                                        q2.x, q2.y, q3.x, q3.y};
            #pragma unroll
            for (int j = 0; j < 8; j++) {
                ffma2(acc[0][j], pa0, bb[j]);
                ffma2(acc[1][j], pa1, bb[j]);
                ffma2(acc[2][j], pa2, bb[j]);
                ffma2(acc[3][j], pa3, bb[j]);
            }
        }
        if (kt < 7) {
            float4* dst = (float4*)(w1s + ((kt + 1) & 1) * (BK * D));
            #pragma unroll
            for (int t = 0; t < 8; t++) dst[tid + t * NT] = stage[t];
            __syncthreads();
        }
    }

    // ---- epilogue: +b1, relu, dot with W2 -> per-thread partials ----
    float b1r[16], w2r[16];
    #pragma unroll
    for (int j = 0; j < 16; j++) {
        b1r[j] = b1[cg * 16 + j];
        w2r[j] = W2[cg * 16 + j];
    }
    float p[4] = {0.f, 0.f, 0.f, 0.f};
    #pragma unroll
    for (int i = 0; i < 4; i++) {
        #pragma unroll
        for (int j = 0; j < 8; j++) {
            float2 v = unpack2(acc[i][j]);
            float h0 = v.x + b1r[2 * j];
            float h1 = v.y + b1r[2 * j + 1];
            h0 = h0 > 0.f ? h0 : 0.f;
            h1 = h1 > 0.f ? h1 : 0.f;
            p[i] += h0 * w2r[2 * j] + h1 * w2r[2 * j + 1];
        }
    }

    // ---- cross-column-group reduction through smem (reuse w1s) ----
    __syncthreads();
    float* red = w1s;                   // [16][64]
    #pragma unroll
    for (int i = 0; i < 4; i++) red[cg * BM + eg * 4 + i] = p[i];
    __syncthreads();

    if (tid < BM) {
        float s = b2[0];
        #pragma unroll
        for (int c = 0; c < 16; c++) s += red[c * BM + tid];
        int e = e0 + tid;
        if (e < E) out[e] = s;
    }
}

extern "C" void kernel_launch(void* const* d_in, const int* in_sizes, int n_in,
                              void* d_out, int out_size)
{
    const float* h     = (const float*)d_in[0];
    const void*  edges = (const void*)d_in[1];
    const float* W1    = (const float*)d_in[2];
    const float* b1    = (const float*)d_in[3];
    const float* W2    = (const float*)d_in[4];
    const float* b2    = (const float*)d_in[5];
    float* out = (float*)d_out;

    int E = in_sizes[1] / 2;            // edges is [E,2]
    int grid = (E + BM - 1) / BM;
    size_t smem = (size_t)(D * BM + 2 * BK * D) * sizeof(float);  // 128 KB

    cudaFuncSetAttribute(mlpdec_kernel,
                         cudaFuncAttributeMaxDynamicSharedMemorySize,
                         (int)smem);
    mlpdec_kernel<<<grid, NT, smem>>>(h, edges, W1, b1, W2, b2, out, E);
}

// round 5
// speedup vs baseline: 1.6640x; 1.6608x over previous
#include <cuda_runtime.h>
#include <cuda_fp16.h>
#include <cstdint>

#define D    256
#define BM   64            // edges per CTA
#define KC   64            // K chunk
#define NT   256

// ---- smem byte offsets ----
#define AHI_OFF   0        // [64 rows][512B]  (256 fp16 per row, swizzled) 32KB
#define ALO_OFF   32768
#define BBUF_OFF  65536    // buf b at +b*65536; hi at +0, lo at +32768 (2 bufs = 128KB)
#define EIDX_OFF  196608   // 128 ints
#define B1S_OFF   (EIDX_OFF + 512)
#define W2S_OFF   (B1S_OFF + 1024)
#define RED_OFF   (W2S_OFF + 1024)   // 128 floats
#define SMEM_TOTAL (RED_OFF + 512)   // 199680

// W1^T preconverted to fp16 hi/lo in final swizzled tile layout:
// chunk c (k = 64c..64c+63): 64KB blob = [hi 32KB][lo 32KB],
// hi/lo blob: byte = kk*512 + ((nchunk ^ (kk&7))<<4) + (n&7)*2
__device__ __align__(16) char g_Bprep[262144];

__device__ __forceinline__ uint32_t smem_u32(const void* p) {
    uint32_t a;
    asm("{ .reg .u64 t; cvta.to.shared.u64 t, %1; cvt.u32.u64 %0, t; }"
        : "=r"(a) : "l"(p));
    return a;
}
__device__ __forceinline__ void cp16(uint32_t dst, const void* src) {
    asm volatile("{ .reg .u64 g; cvta.to.global.u64 g, %1;"
                 " cp.async.cg.shared.global [%0], [g], 16; }"
                 :: "r"(dst), "l"(src) : "memory");
}
__device__ __forceinline__ void ldsm4(uint32_t& r0, uint32_t& r1,
                                      uint32_t& r2, uint32_t& r3, uint32_t a) {
    asm volatile("ldmatrix.sync.aligned.m8n8.x4.shared.b16 {%0,%1,%2,%3}, [%4];"
                 : "=r"(r0), "=r"(r1), "=r"(r2), "=r"(r3) : "r"(a));
}
__device__ __forceinline__ void ldsm4t(uint32_t& r0, uint32_t& r1,
                                       uint32_t& r2, uint32_t& r3, uint32_t a) {
    asm volatile("ldmatrix.sync.aligned.m8n8.x4.trans.shared.b16 {%0,%1,%2,%3}, [%4];"
                 : "=r"(r0), "=r"(r1), "=r"(r2), "=r"(r3) : "r"(a));
}
__device__ __forceinline__ void mma16816(float* c,
                                         uint32_t a0, uint32_t a1,
                                         uint32_t a2, uint32_t a3,
                                         uint32_t b0, uint32_t b1) {
    asm volatile("mma.sync.aligned.m16n8k16.row.col.f32.f16.f16.f32 "
                 "{%0,%1,%2,%3}, {%4,%5,%6,%7}, {%8,%9}, {%0,%1,%2,%3};"
                 : "+f"(c[0]), "+f"(c[1]), "+f"(c[2]), "+f"(c[3])
                 : "r"(a0), "r"(a1), "r"(a2), "r"(a3), "r"(b0), "r"(b1));
}

// ---- prep: W1 [k][n] f32 -> fp16 hi/lo, swizzled tile blobs ----
__global__ void prep_w1(const float* __restrict__ W1) {
    int k = blockIdx.x;     // 0..255
    int n = threadIdx.x;    // 0..255
    float w = W1[k * D + n];
    __half hi = __float2half_rn(w);
    __half lo = __float2half_rn(w - __half2float(hi));
    int c = k >> 6, kk = k & 63;
    uint32_t base = (uint32_t)c * 65536u + (uint32_t)kk * 512u
                  + ((uint32_t)(((n >> 3) ^ (kk & 7)) & 31) << 4)
                  + (uint32_t)(n & 7) * 2u;
    *(__half*)(g_Bprep + base)         = hi;
    *(__half*)(g_Bprep + base + 32768) = lo;
}

__global__ __launch_bounds__(NT, 1)
void mlpdec_mma(const float* __restrict__ h,
                const void* __restrict__ edges_raw,
                const float* __restrict__ b1,
                const float* __restrict__ W2,
                const float* __restrict__ b2,
                float* __restrict__ out,
                int E)
{
    extern __shared__ char smem[];
    const uint32_t sb = smem_u32(smem);
    const int tid  = threadIdx.x;
    const int lane = tid & 31;
    const int wid  = tid >> 5;
    const int e0   = blockIdx.x * BM;

    int*   eidx = (int*)(smem + EIDX_OFF);
    float* b1s  = (float*)(smem + B1S_OFF);
    float* w2s  = (float*)(smem + W2S_OFF);
    float* red  = (float*)(smem + RED_OFF);

    // ---- kick off B chunk 0 copy immediately ----
    {
        const char* src = g_Bprep + tid * 16;
        uint32_t dst = sb + BBUF_OFF + tid * 16;
        #pragma unroll
        for (int i = 0; i < 16; i++) cp16(dst + i * 4096, src + i * 4096);
        asm volatile("cp.async.commit_group;" ::: "memory");
    }

    // ---- edge dtype probe (int64 of values <100000 has zero odd dwords) ----
    const int* w32 = (const int*)edges_raw;
    bool is64 = true;
    #pragma unroll
    for (int i = 0; i < 8; i++)
        if (w32[2 * i + 1] != 0) { is64 = false; break; }

    if (tid < BM) {
        long long e = (long long)e0 + tid;
        int s = 0, d = 0;
        if (e < E) {
            if (is64) {
                const long long* e64 = (const long long*)edges_raw;
                s = (int)e64[2 * e];
                d = (int)e64[2 * e + 1];
            } else {
                s = w32[2 * e];
                d = w32[2 * e + 1];
            }
        }
        eidx[tid]      = s;
        eidx[BM + tid] = d;
    }
    b1s[tid] = b1[tid];
    w2s[tid] = W2[tid];
    __syncthreads();

    // ---- produce A: hadamard -> fp16 hi/lo, swizzled ----
    {
        int row = tid & 63;
        int q   = tid >> 6;            // 0..3, covers k = q*64 .. q*64+63
        int s = eidx[row], d = eidx[BM + row];
        const float4* hs = (const float4*)(h + (size_t)s * D) + q * 16;
        const float4* hd = (const float4*)(h + (size_t)d * D) + q * 16;
        #pragma unroll
        for (int j = 0; j < 8; j++) {      // 8 chunks of 8 halfs
            float4 a0 = hs[2 * j], a1 = hs[2 * j + 1];
            float4 c0 = hd[2 * j], c1 = hd[2 * j + 1];
            float p[8] = { a0.x * c0.x, a0.y * c0.y, a0.z * c0.z, a0.w * c0.w,
                           a1.x * c1.x, a1.y * c1.y, a1.z * c1.z, a1.w * c1.w };
            union { __half hh[8]; uint4 v; } uhi, ulo;
            #pragma unroll
            for (int t = 0; t < 8; t++) {
                __half hv = __float2half_rn(p[t]);
                uhi.hh[t] = hv;
                ulo.hh[t] = __float2half_rn(p[t] - __half2float(hv));
            }
            int chunk = q * 8 + j;
            uint32_t byte = (uint32_t)row * 512u
                          + ((uint32_t)(chunk ^ (row & 7)) << 4);
            *(uint4*)(smem + AHI_OFF + byte) = uhi.v;
            *(uint4*)(smem + ALO_OFF + byte) = ulo.v;
        }
    }

    // ---- warp tiling: 4 M-groups x 2 N-groups ----
    const int rm = (wid & 3) * 16;      // row base (16 rows per warp)
    const int wn = wid >> 2;            // 0/1 -> 128-col half
    float acc[16][4];
    #pragma unroll
    for (int i = 0; i < 16; i++)
        #pragma unroll
        for (int j = 0; j < 4; j++) acc[i][j] = 0.f;

    const int arow = rm + (lane & 15);
    const uint32_t Ah = sb + AHI_OFF;
    const uint32_t Al = sb + ALO_OFF;

    // ---- main loop: 4 K-chunks, double-buffered B via cp.async ----
    #pragma unroll 1
    for (int c = 0; c < 4; c++) {
        const int buf = c & 1;
        if (c < 3) {
            const char* src = g_Bprep + (c + 1) * 65536 + tid * 16;
            uint32_t dst = sb + BBUF_OFF + ((c + 1) & 1) * 65536 + tid * 16;
            #pragma unroll
            for (int i = 0; i < 16; i++) cp16(dst + i * 4096, src + i * 4096);
            asm volatile("cp.async.commit_group;" ::: "memory");
            asm volatile("cp.async.wait_group 1;" ::: "memory");
        } else {
            asm volatile("cp.async.wait_group 0;" ::: "memory");
        }
        __syncthreads();

        const uint32_t Bh = sb + BBUF_OFF + buf * 65536;
        const uint32_t Bl = Bh + 32768;

        #pragma unroll
        for (int ks = 0; ks < 4; ks++) {
            const int kg = c * 4 + ks;                    // global k-step
            const int achunk = kg * 2 + (lane >> 4);
            const uint32_t aaddr = (uint32_t)arow * 512u
                                 + ((uint32_t)(achunk ^ (arow & 7)) << 4);
            uint32_t ah0, ah1, ah2, ah3, al0, al1, al2, al3;
            ldsm4(ah0, ah1, ah2, ah3, Ah + aaddr);
            ldsm4(al0, al1, al2, al3, Al + aaddr);

            const int kk = ks * 16 + (lane & 7) + ((lane >> 3) & 1) * 8;
            const uint32_t brow = (uint32_t)kk * 512u;

            #pragma unroll
            for (int nt2 = 0; nt2 < 8; nt2++) {
                const int ch = wn * 16 + nt2 * 2 + (lane >> 4);
                const uint32_t baddr = brow
                                     + ((uint32_t)(ch ^ (kk & 7)) << 4);
                uint32_t bh0, bh1, bh2, bh3, bl0, bl1, bl2, bl3;
                ldsm4t(bh0, bh1, bh2, bh3, Bh + baddr);
                ldsm4t(bl0, bl1, bl2, bl3, Bl + baddr);
                float* c0 = acc[nt2 * 2];
                float* c1 = acc[nt2 * 2 + 1];
                mma16816(c0, ah0, ah1, ah2, ah3, bh0, bh1);
                mma16816(c1, ah0, ah1, ah2, ah3, bh2, bh3);
                mma16816(c0, ah0, ah1, ah2, ah3, bl0, bl1);
                mma16816(c1, ah0, ah1, ah2, ah3, bl2, bl3);
                mma16816(c0, al0, al1, al2, al3, bh0, bh1);
                mma16816(c1, al0, al1, al2, al3, bh2, bh3);
            }
        }
        __syncthreads();
    }

    // ---- epilogue: +b1, ReLU, dot W2 ----
    {
        float plo = 0.f, phi = 0.f;
        #pragma unroll
        for (int nt = 0; nt < 16; nt++) {
            int n0 = wn * 128 + nt * 8 + (lane & 3) * 2;
            float v0 = acc[nt][0] + b1s[n0];
            float v1 = acc[nt][1] + b1s[n0 + 1];
            float v2 = acc[nt][2] + b1s[n0];
            float v3 = acc[nt][3] + b1s[n0 + 1];
            v0 = v0 > 0.f ? v0 : 0.f;
            v1 = v1 > 0.f ? v1 : 0.f;
            v2 = v2 > 0.f ? v2 : 0.f;
            v3 = v3 > 0.f ? v3 : 0.f;
            plo += v0 * w2s[n0] + v1 * w2s[n0 + 1];
            phi += v2 * w2s[n0] + v3 * w2s[n0 + 1];
        }
        plo += __shfl_xor_sync(0xFFFFFFFFu, plo, 1);
        plo += __shfl_xor_sync(0xFFFFFFFFu, plo, 2);
        phi += __shfl_xor_sync(0xFFFFFFFFu, phi, 1);
        phi += __shfl_xor_sync(0xFFFFFFFFu, phi, 2);
        if ((lane & 3) == 0) {
            int r = rm + (lane >> 2);
            red[wn * 64 + r]     = plo;
            red[wn * 64 + r + 8] = phi;
        }
    }
    __syncthreads();

    if (tid < BM) {
        int e = e0 + tid;
        if (e < E) out[e] = red[tid] + red[64 + tid] + b2[0];
    }
}

extern "C" void kernel_launch(void* const* d_in, const int* in_sizes, int n_in,
                              void* d_out, int out_size)
{
    const float* h     = (const float*)d_in[0];
    const void*  edges = (const void*)d_in[1];
    const float* W1    = (const float*)d_in[2];
    const float* b1    = (const float*)d_in[3];
    const float* W2    = (const float*)d_in[4];
    const float* b2    = (const float*)d_in[5];
    float* out = (float*)d_out;

    int E = in_sizes[1] / 2;

    prep_w1<<<D, D>>>(W1);

    int grid = (E + BM - 1) / BM;
    cudaFuncSetAttribute(mlpdec_mma,
                         cudaFuncAttributeMaxDynamicSharedMemorySize,
                         SMEM_TOTAL);
    mlpdec_mma<<<grid, NT, SMEM_TOTAL>>>(h, edges, b1, W2, b2, out, E);
}